// round 10
// baseline (speedup 1.0000x reference)
#include <cuda_runtime.h>
#include <cuda_fp16.h>
#include <cstdint>

#define NROW 1024
#define KDIM 2048
#define NF   128
#define SPLITK 4
#define KCHUNK (KDIM / SPLITK)   // 512
#define BK 64
#define MTILES 32                // 2048 rows / 64

// ---------------------------------------------------------------------------
// Device scratch
// ---------------------------------------------------------------------------
__device__ float    g_part[SPLITK * 2048 * NF];  // split-K partials [ks][m][n] 4MB
__device__ __half   g_shi[2048 * NF];            // relu(scores) fp16, [m][k]
__device__ unsigned g_cnt[MTILES];               // arrival counters (self-reset)

// ---------------------------------------------------------------------------
// Helpers
// ---------------------------------------------------------------------------
__device__ __forceinline__ uint32_t su32(const void* p) {
    return (uint32_t)__cvta_generic_to_shared(p);
}
__device__ __forceinline__ uint32_t pk(__half a, __half b) {
    __half2 h = __halves2half2(a, b);
    return *reinterpret_cast<uint32_t*>(&h);
}
__device__ __forceinline__ void cp16(uint32_t dst, const void* src) {
    asm volatile("cp.async.ca.shared.global [%0], [%1], 16;" :: "r"(dst), "l"(src));
}

#define CP_COMMIT() asm volatile("cp.async.commit_group;" ::: "memory")
#define CP_WAIT0()  asm volatile("cp.async.wait_group 0;"  ::: "memory")
#define CP_WAIT1()  asm volatile("cp.async.wait_group 1;"  ::: "memory")

#define LDSM4(R, addr) \
    asm volatile("ldmatrix.sync.aligned.m8n8.x4.shared.b16 {%0,%1,%2,%3}, [%4];" \
        : "=r"((R)[0]), "=r"((R)[1]), "=r"((R)[2]), "=r"((R)[3]) : "r"(addr))

#define MMA(C, A, b0, b1) \
    asm volatile("mma.sync.aligned.m16n8k16.row.col.f32.f16.f16.f32 " \
        "{%0,%1,%2,%3}, {%4,%5,%6,%7}, {%8,%9}, {%0,%1,%2,%3};" \
        : "+f"((C)[0]), "+f"((C)[1]), "+f"((C)[2]), "+f"((C)[3]) \
        : "r"((A)[0]), "r"((A)[1]), "r"((A)[2]), "r"((A)[3]), "r"(b0), "r"(b1))

// swizzled byte offset, 128B rows (64 halves)
__device__ __forceinline__ uint32_t swz1(int row, int kh) {
    return (uint32_t)(row * 128 + ((((kh >> 3) ^ (row & 7)) << 4)));
}
// swizzled byte offset, 256B rows (128 halves)
__device__ __forceinline__ uint32_t swz2(int row, int kh) {
    int c = kh >> 3;
    return (uint32_t)(row * 256 + ((((c & 8) | ((c ^ (row & 7)) & 7)) << 4)));
}

__device__ __forceinline__ uint2 round4(float4 v) {
    uint2 hw;
    hw.x = pk(__float2half_rn(v.x), __float2half_rn(v.y));
    hw.y = pk(__float2half_rn(v.z), __float2half_rn(v.w));
    return hw;
}

// ---------------------------------------------------------------------------
// Stage 1: partial[ks][m 64-tile][0..127] = X[m, kchunk] . feats^T  (fp16 MMA)
// grid (32 m-tiles, 4 ks), 512 threads (16 warps, warp tile 32m x 16n).
// smem per buffer (24576B): X +0 (8KB), F +8192 (16KB); two buffers = 48KB.
// Tail: last CTA of each m-tile reduces 4 planes -> relu -> fp16 g_shi.
// ---------------------------------------------------------------------------
__global__ __launch_bounds__(512, 1) void stage1(const float* __restrict__ A_,
                                                 const float* __restrict__ B_,
                                                 const float* __restrict__ F_) {
    extern __shared__ char smem[];
    __shared__ int s_last;
    const uint32_t sb = su32(smem);
    const int t = threadIdx.x, lane = t & 31, wid = t >> 5;
    const int mt_idx = blockIdx.x;
    const int m0 = mt_idx * 64;
    const int ks = blockIdx.y;
    const float* X = (m0 < NROW) ? A_ : B_;
    const int mb = (m0 < NROW) ? m0 : m0 - NROW;
    const int kbase = ks * KCHUNK;

    const int wy = wid & 1, wx = wid >> 1;
    const int m0w = wy * 32, n0w = wx * 16;
    const int aRow = lane & 15, aK = (lane >> 4) << 3;
    const int bN = ((lane >> 4) << 3) + (lane & 7), bK = ((lane >> 3) & 1) << 3;

    // load mappings
    const int xrow = t >> 3, xc = t & 7;        // X: 64 rows, 8 chunks each
    int frow[2], fc[2];                          // F: 128 rows
    #pragma unroll
    for (int i = 0; i < 2; i++) {
        int chunk = t + i * 512;
        frow[i] = chunk >> 3;
        fc[i]   = chunk & 7;
    }

    float acc[2][2][4];
    #pragma unroll
    for (int i = 0; i < 2; i++)
        #pragma unroll
        for (int j = 0; j < 2; j++)
            #pragma unroll
            for (int q = 0; q < 4; q++) acc[i][j][q] = 0.f;

    float xr[8], fr[2][8];

    // ---- slab 0 prologue ----
    {
        const int kk = kbase;
        const float* sx = &X[(size_t)(mb + xrow) * KDIM + kk + xc * 8];
        *(float4*)&xr[0] = *(const float4*)sx;
        *(float4*)&xr[4] = *(const float4*)(sx + 4);
        #pragma unroll
        for (int i = 0; i < 2; i++) {
            const float* sf = &F_[(size_t)frow[i] * KDIM + kk + fc[i] * 8];
            *(float4*)&fr[i][0] = *(const float4*)sf;
            *(float4*)&fr[i][4] = *(const float4*)(sf + 4);
        }
        {
            uint32_t off = (uint32_t)(xrow * 128 + (((xc ^ (xrow & 7)) << 4)));
            uint2 x0 = round4(*(float4*)&xr[0]);
            uint2 x1 = round4(*(float4*)&xr[4]);
            *(uint4*)(smem + off) = make_uint4(x0.x, x0.y, x1.x, x1.y);
        }
        #pragma unroll
        for (int i = 0; i < 2; i++) {
            uint32_t off = (uint32_t)(frow[i] * 128 + (((fc[i] ^ (frow[i] & 7)) << 4)));
            uint2 f0 = round4(*(float4*)&fr[i][0]);
            uint2 f1 = round4(*(float4*)&fr[i][4]);
            *(uint4*)(smem + 8192 + off) = make_uint4(f0.x, f0.y, f1.x, f1.y);
        }
        __syncthreads();
    }

    // ---- main loop over 8 slabs ----
    #pragma unroll 1
    for (int s = 0; s < 8; s++) {
        const int p = s & 1, np = p ^ 1;
        if (s < 7) {
            const int kk = kbase + (s + 1) * BK;
            const float* sx = &X[(size_t)(mb + xrow) * KDIM + kk + xc * 8];
            *(float4*)&xr[0] = *(const float4*)sx;
            *(float4*)&xr[4] = *(const float4*)(sx + 4);
            #pragma unroll
            for (int i = 0; i < 2; i++) {
                const float* sf = &F_[(size_t)frow[i] * KDIM + kk + fc[i] * 8];
                *(float4*)&fr[i][0] = *(const float4*)sf;
                *(float4*)&fr[i][4] = *(const float4*)(sf + 4);
            }
        }

        const uint32_t base = sb + p * 24576;
        #pragma unroll
        for (int k16 = 0; k16 < 4; k16++) {
            const int kh = k16 * 16;
            uint32_t ah[2][4], bh[4];
            #pragma unroll
            for (int mt = 0; mt < 2; mt++) {
                uint32_t ra = base + swz1(m0w + mt * 16 + aRow, kh + aK);
                LDSM4(ah[mt], ra);
            }
            {
                uint32_t rb = base + 8192 + swz1(n0w + bN, kh + bK);
                LDSM4(bh, rb);
            }
            #pragma unroll
            for (int mt = 0; mt < 2; mt++)
                #pragma unroll
                for (int nt = 0; nt < 2; nt++) {
                    uint32_t h0 = bh[nt * 2], h1 = bh[nt * 2 + 1];
                    MMA(acc[mt][nt], ah[mt], h0, h1);
                }
        }

        if (s < 7) {
            const uint32_t nboff = (uint32_t)(np * 24576);
            {
                uint32_t off = nboff + (uint32_t)(xrow * 128 + (((xc ^ (xrow & 7)) << 4)));
                uint2 x0 = round4(*(float4*)&xr[0]);
                uint2 x1 = round4(*(float4*)&xr[4]);
                *(uint4*)(smem + off) = make_uint4(x0.x, x0.y, x1.x, x1.y);
            }
            #pragma unroll
            for (int i = 0; i < 2; i++) {
                uint32_t off = nboff + (uint32_t)(frow[i] * 128 + (((fc[i] ^ (frow[i] & 7)) << 4)));
                uint2 f0 = round4(*(float4*)&fr[i][0]);
                uint2 f1 = round4(*(float4*)&fr[i][4]);
                *(uint4*)(smem + 8192 + off) = make_uint4(f0.x, f0.y, f1.x, f1.y);
            }
        }
        __syncthreads();
    }

    // ---- epilogue: write fp32 partials ----
    float* dst = g_part + (size_t)ks * (2048 * NF);
    #pragma unroll
    for (int mt = 0; mt < 2; mt++)
        #pragma unroll
        for (int nt = 0; nt < 2; nt++) {
            int r = m0 + m0w + mt * 16 + (lane >> 2);
            int cc = n0w + nt * 8 + (lane & 3) * 2;
            *(float2*)&dst[(size_t)r * NF + cc] =
                make_float2(acc[mt][nt][0], acc[mt][nt][1]);
            *(float2*)&dst[(size_t)(r + 8) * NF + cc] =
                make_float2(acc[mt][nt][2], acc[mt][nt][3]);
        }

    // ---- last CTA of this m-tile reduces the 4 planes ----
    __threadfence();
    if (t == 0) {
        unsigned old = atomicAdd(&g_cnt[mt_idx], 1);
        s_last = (old == SPLITK - 1);
    }
    __syncthreads();
    if (s_last) {
        // 64 rows x 128 cols = 2048 float4; 4 per thread
        #pragma unroll
        for (int i = 0; i < 4; i++) {
            int idx = t + i * 512;                        // 0..2047
            size_t o = (size_t)m0 * NF + (size_t)idx * 4;
            float4 s = make_float4(0.f, 0.f, 0.f, 0.f);
            #pragma unroll
            for (int p = 0; p < SPLITK; p++) {
                float4 v = *(const float4*)&g_part[(size_t)p * (2048 * NF) + o];
                s.x += v.x; s.y += v.y; s.z += v.z; s.w += v.w;
            }
            s.x = fmaxf(s.x, 0.f); s.y = fmaxf(s.y, 0.f);
            s.z = fmaxf(s.z, 0.f); s.w = fmaxf(s.w, 0.f);
            *(uint2*)&g_shi[o] = round4(s);
        }
        if (t == 0) {
            __threadfence();
            g_cnt[mt_idx] = 0;                            // reset for next replay
        }
    }
}

// ---------------------------------------------------------------------------
// Stage 2: out[i][j] = sum_k shi[i][k] * shi[1024+j][k]
// grid (16 j, 8 i): CTA 128i x 64j, 512 threads (warp tile 32i x 16j).
// smem: AHI +0 (32KB), BHI +32768 (16KB) = 48KB, cp.async 2 K-half groups.
// ---------------------------------------------------------------------------
__global__ __launch_bounds__(512, 1) void stage2(float* __restrict__ out) {
    extern __shared__ char smem[];
    const uint32_t sb = su32(smem);
    const int t = threadIdx.x, lane = t & 31, wid = t >> 5;
    const int it = blockIdx.y * 128, jt = blockIdx.x * 64;
    const int wy = wid & 3, wx = wid >> 2;
    const int m0w = wy * 32, n0w = wx * 16;

    // two K-half commit groups: group cc covers kh [cc*64, cc*64+64)
    #pragma unroll
    for (int cc = 0; cc < 2; cc++) {
        #pragma unroll
        for (int i = 0; i < 2; i++) {
            int idx = t + i * 512;                 // 0..1023
            int row = idx >> 3, c = (idx & 7) + cc * 8;
            uint32_t off = swz2(row, c * 8);
            cp16(sb + off, &g_shi[(size_t)(it + row) * NF + c * 8]);
        }
        {
            int row = t >> 3, c = (t & 7) + cc * 8;   // 512 -> 64 rows
            uint32_t off = swz2(row, c * 8);
            cp16(sb + 32768 + off, &g_shi[(size_t)(1024 + jt + row) * NF + c * 8]);
        }
        CP_COMMIT();
    }

    const int aRow = lane & 15, aK = (lane >> 4) << 3;
    const int bN = ((lane >> 4) << 3) + (lane & 7), bK = ((lane >> 3) & 1) << 3;

    float acc[2][2][4];
    #pragma unroll
    for (int i = 0; i < 2; i++)
        #pragma unroll
        for (int j = 0; j < 2; j++)
            #pragma unroll
            for (int q = 0; q < 4; q++) acc[i][j][q] = 0.f;

    CP_WAIT1();
    __syncthreads();

    #pragma unroll
    for (int half = 0; half < 2; half++) {
        #pragma unroll
        for (int k16 = 0; k16 < 4; k16++) {
            const int kh = half * 64 + k16 * 16;
            uint32_t ah[2][4], bh[4];
            #pragma unroll
            for (int mt = 0; mt < 2; mt++) {
                uint32_t ra = sb + swz2(m0w + mt * 16 + aRow, kh + aK);
                LDSM4(ah[mt], ra);
            }
            {
                uint32_t rb = sb + 32768 + swz2(n0w + bN, kh + bK);
                LDSM4(bh, rb);
            }
            #pragma unroll
            for (int mt = 0; mt < 2; mt++)
                #pragma unroll
                for (int nt = 0; nt < 2; nt++) {
                    uint32_t h0 = bh[nt * 2], h1 = bh[nt * 2 + 1];
                    MMA(acc[mt][nt], ah[mt], h0, h1);
                }
        }
        if (half == 0) {
            CP_WAIT0();
            __syncthreads();
        }
    }

    #pragma unroll
    for (int mt = 0; mt < 2; mt++)
        #pragma unroll
        for (int nt = 0; nt < 2; nt++) {
            int r = it + m0w + mt * 16 + (lane >> 2);
            int cc = jt + n0w + nt * 8 + (lane & 3) * 2;
            *(float2*)&out[(size_t)r * NROW + cc] =
                make_float2(acc[mt][nt][0], acc[mt][nt][1]);
            *(float2*)&out[(size_t)(r + 8) * NROW + cc] =
                make_float2(acc[mt][nt][2], acc[mt][nt][3]);
        }
}

// ---------------------------------------------------------------------------
extern "C" void kernel_launch(void* const* d_in, const int* in_sizes, int n_in,
                              void* d_out, int out_size) {
    (void)in_sizes; (void)n_in; (void)out_size;
    const float* a = (const float*)d_in[0];
    const float* b = (const float*)d_in[1];
    const float* f = (const float*)d_in[2];
    float* out = (float*)d_out;

    cudaFuncSetAttribute(stage1, cudaFuncAttributeMaxDynamicSharedMemorySize, 49152);
    cudaFuncSetAttribute(stage2, cudaFuncAttributeMaxDynamicSharedMemorySize, 49152);

    stage1<<<dim3(MTILES, SPLITK), 512, 49152>>>(a, b, f);
    stage2<<<dim3(16, 8), 512, 49152>>>(out);
}

// round 11
// speedup vs baseline: 1.0935x; 1.0935x over previous
#include <cuda_runtime.h>
#include <cuda_fp16.h>
#include <cstdint>

#define NROW 1024
#define KDIM 2048
#define NF   128
#define SPLITK 8
#define KCHUNK (KDIM / SPLITK)   // 256
#define BK 64
#define MTILES 16                // 2048 rows / 128

// ---------------------------------------------------------------------------
// Device scratch
// ---------------------------------------------------------------------------
__device__ float    g_part[SPLITK * 2048 * NF];  // split-K partials [ks][m][n]
__device__ __half   g_shi[2048 * NF];            // relu(scores) fp16, [m][k]
__device__ unsigned g_arr[MTILES];               // monotonic arrival counters

// ---------------------------------------------------------------------------
// Helpers
// ---------------------------------------------------------------------------
__device__ __forceinline__ uint32_t su32(const void* p) {
    return (uint32_t)__cvta_generic_to_shared(p);
}
__device__ __forceinline__ uint32_t pk(__half a, __half b) {
    __half2 h = __halves2half2(a, b);
    return *reinterpret_cast<uint32_t*>(&h);
}
__device__ __forceinline__ void cp16(uint32_t dst, const void* src) {
    asm volatile("cp.async.ca.shared.global [%0], [%1], 16;" :: "r"(dst), "l"(src));
}

#define CP_COMMIT() asm volatile("cp.async.commit_group;" ::: "memory")
#define CP_WAIT0()  asm volatile("cp.async.wait_group 0;"  ::: "memory")
#define CP_WAIT1()  asm volatile("cp.async.wait_group 1;"  ::: "memory")

#define LDSM4(R, addr) \
    asm volatile("ldmatrix.sync.aligned.m8n8.x4.shared.b16 {%0,%1,%2,%3}, [%4];" \
        : "=r"((R)[0]), "=r"((R)[1]), "=r"((R)[2]), "=r"((R)[3]) : "r"(addr))

#define MMA(C, A, b0, b1) \
    asm volatile("mma.sync.aligned.m16n8k16.row.col.f32.f16.f16.f32 " \
        "{%0,%1,%2,%3}, {%4,%5,%6,%7}, {%8,%9}, {%0,%1,%2,%3};" \
        : "+f"((C)[0]), "+f"((C)[1]), "+f"((C)[2]), "+f"((C)[3]) \
        : "r"((A)[0]), "r"((A)[1]), "r"((A)[2]), "r"((A)[3]), "r"(b0), "r"(b1))

// swizzled byte offset, 128B rows (64 halves)
__device__ __forceinline__ uint32_t swz1(int row, int kh) {
    return (uint32_t)(row * 128 + ((((kh >> 3) ^ (row & 7)) << 4)));
}
// swizzled byte offset, 256B rows (128 halves)
__device__ __forceinline__ uint32_t swz2(int row, int kh) {
    int c = kh >> 3;
    return (uint32_t)(row * 256 + ((((c & 8) | ((c ^ (row & 7)) & 7)) << 4)));
}

__device__ __forceinline__ uint2 round4(float4 v) {
    uint2 hw;
    hw.x = pk(__float2half_rn(v.x), __float2half_rn(v.y));
    hw.y = pk(__float2half_rn(v.z), __float2half_rn(v.w));
    return hw;
}

// ---------------------------------------------------------------------------
// Stage 1: partial[ks][m 128-tile][0..127] = X[m, kchunk] . feats^T (fp16 MMA)
// grid (16 m, 8 ks), 512 threads (16 warps, warp tile 32m x 32n).
// F converted inline from fp32 (no prep kernel).
// smem per buffer (32768B): X +0 (16KB), F +16384 (16KB); two buffers = 64KB.
// Tail: per-m-tile monotonic barrier, then each split-CTA reduces its own
// 16-row slice of the 8 partial planes -> relu -> fp16 g_shi.
// ---------------------------------------------------------------------------
__global__ __launch_bounds__(512, 1) void stage1(const float* __restrict__ A_,
                                                 const float* __restrict__ B_,
                                                 const float* __restrict__ F_) {
    extern __shared__ char smem[];
    const int t = threadIdx.x, lane = t & 31, wid = t >> 5;
    const uint32_t sb = su32(smem);
    const int mt_idx = blockIdx.x;
    const int m0 = mt_idx * 128;
    const int ks = blockIdx.y;
    const float* X = (m0 < NROW) ? A_ : B_;
    const int mb = (m0 < NROW) ? m0 : m0 - NROW;
    const int kbase = ks * KCHUNK;

    const int wy = wid & 3, wx = wid >> 2;
    const int m0w = wy * 32, n0w = wx * 32;
    const int aRow = lane & 15, aK = (lane >> 4) << 3;
    const int bN = ((lane >> 4) << 3) + (lane & 7), bK = ((lane >> 3) & 1) << 3;

    float acc[2][4][4];
    #pragma unroll
    for (int i = 0; i < 2; i++)
        #pragma unroll
        for (int j = 0; j < 4; j++)
            #pragma unroll
            for (int q = 0; q < 4; q++) acc[i][j][q] = 0.f;

    float xr[2][8], fr[2][8];

    // per-thread tile coords (constant across slabs): 128 rows x 8 chunks
    int rows_[2], cs_[2];
    #pragma unroll
    for (int i = 0; i < 2; i++) {
        int chunk = t + i * 512;
        rows_[i] = chunk >> 3;
        cs_[i]   = chunk & 7;
    }

    // ---- slab 0 prologue ----
    {
        const int kk = kbase;
        #pragma unroll
        for (int i = 0; i < 2; i++) {
            const float* sx = &X[(size_t)(mb + rows_[i]) * KDIM + kk + cs_[i] * 8];
            const float* sf = &F_[(size_t)rows_[i] * KDIM + kk + cs_[i] * 8];
            *(float4*)&xr[i][0] = *(const float4*)sx;
            *(float4*)&xr[i][4] = *(const float4*)(sx + 4);
            *(float4*)&fr[i][0] = *(const float4*)sf;
            *(float4*)&fr[i][4] = *(const float4*)(sf + 4);
        }
        #pragma unroll
        for (int i = 0; i < 2; i++) {
            uint32_t off = (uint32_t)(rows_[i] * 128 + (((cs_[i] ^ (rows_[i] & 7)) << 4)));
            uint2 x0 = round4(*(float4*)&xr[i][0]);
            uint2 x1 = round4(*(float4*)&xr[i][4]);
            uint2 f0 = round4(*(float4*)&fr[i][0]);
            uint2 f1 = round4(*(float4*)&fr[i][4]);
            *(uint4*)(smem + off)         = make_uint4(x0.x, x0.y, x1.x, x1.y);
            *(uint4*)(smem + 16384 + off) = make_uint4(f0.x, f0.y, f1.x, f1.y);
        }
        __syncthreads();
    }

    // ---- main loop over 4 slabs ----
    #pragma unroll 1
    for (int s = 0; s < 4; s++) {
        const int p = s & 1, np = p ^ 1;
        if (s < 3) {
            const int kk = kbase + (s + 1) * BK;
            #pragma unroll
            for (int i = 0; i < 2; i++) {
                const float* sx = &X[(size_t)(mb + rows_[i]) * KDIM + kk + cs_[i] * 8];
                const float* sf = &F_[(size_t)rows_[i] * KDIM + kk + cs_[i] * 8];
                *(float4*)&xr[i][0] = *(const float4*)sx;
                *(float4*)&xr[i][4] = *(const float4*)(sx + 4);
                *(float4*)&fr[i][0] = *(const float4*)sf;
                *(float4*)&fr[i][4] = *(const float4*)(sf + 4);
            }
        }

        const uint32_t base = sb + p * 32768;
        #pragma unroll
        for (int k16 = 0; k16 < 4; k16++) {
            const int kh = k16 * 16;
            uint32_t ah[2][4], bh[2][4];
            #pragma unroll
            for (int mt = 0; mt < 2; mt++) {
                uint32_t ra = base + swz1(m0w + mt * 16 + aRow, kh + aK);
                LDSM4(ah[mt], ra);
            }
            #pragma unroll
            for (int g = 0; g < 2; g++) {
                uint32_t rb = base + 16384 + swz1(n0w + g * 16 + bN, kh + bK);
                LDSM4(bh[g], rb);
            }
            #pragma unroll
            for (int mt = 0; mt < 2; mt++)
                #pragma unroll
                for (int nt = 0; nt < 4; nt++) {
                    uint32_t h0 = bh[nt >> 1][(nt & 1) * 2], h1 = bh[nt >> 1][(nt & 1) * 2 + 1];
                    MMA(acc[mt][nt], ah[mt], h0, h1);
                }
        }

        if (s < 3) {
            const uint32_t nboff = (uint32_t)(np * 32768);
            #pragma unroll
            for (int i = 0; i < 2; i++) {
                uint32_t off = nboff + (uint32_t)(rows_[i] * 128 + (((cs_[i] ^ (rows_[i] & 7)) << 4)));
                uint2 x0 = round4(*(float4*)&xr[i][0]);
                uint2 x1 = round4(*(float4*)&xr[i][4]);
                uint2 f0 = round4(*(float4*)&fr[i][0]);
                uint2 f1 = round4(*(float4*)&fr[i][4]);
                *(uint4*)(smem + off)         = make_uint4(x0.x, x0.y, x1.x, x1.y);
                *(uint4*)(smem + 16384 + off) = make_uint4(f0.x, f0.y, f1.x, f1.y);
            }
        }
        __syncthreads();
    }

    // ---- epilogue: write fp32 partials ----
    float* dst = g_part + (size_t)ks * (2048 * NF);
    #pragma unroll
    for (int mt = 0; mt < 2; mt++)
        #pragma unroll
        for (int nt = 0; nt < 4; nt++) {
            int r = m0 + m0w + mt * 16 + (lane >> 2);
            int cc = n0w + nt * 8 + (lane & 3) * 2;
            *(float2*)&dst[(size_t)r * NF + cc] =
                make_float2(acc[mt][nt][0], acc[mt][nt][1]);
            *(float2*)&dst[(size_t)(r + 8) * NF + cc] =
                make_float2(acc[mt][nt][2], acc[mt][nt][3]);
        }

    // ---- per-m-tile monotonic barrier (replay-safe, no reset) ----
    __threadfence();
    __syncthreads();
    if (t == 0) {
        unsigned old = atomicAdd(&g_arr[mt_idx], 1u);
        unsigned target = ((old >> 3) + 1u) << 3;    // next multiple of 8
        unsigned cur;
        do {
            asm volatile("ld.volatile.global.u32 %0, [%1];"
                         : "=r"(cur) : "l"(&g_arr[mt_idx]));
        } while (cur < target);
    }
    __syncthreads();
    __threadfence();

    // ---- distributed reduce: this CTA handles rows [m0+ks*16, +16) ----
    {
        const int r0 = m0 + ks * 16;
        // 16 rows x 128 cols = 512 float4; one per thread
        size_t o = (size_t)(r0 + (t >> 5)) * NF + (size_t)(t & 31) * 4;
        float4 s = make_float4(0.f, 0.f, 0.f, 0.f);
        #pragma unroll
        for (int p = 0; p < SPLITK; p++) {
            float4 v = *(const float4*)&g_part[(size_t)p * (2048 * NF) + o];
            s.x += v.x; s.y += v.y; s.z += v.z; s.w += v.w;
        }
        s.x = fmaxf(s.x, 0.f); s.y = fmaxf(s.y, 0.f);
        s.z = fmaxf(s.z, 0.f); s.w = fmaxf(s.w, 0.f);
        *(uint2*)&g_shi[o] = round4(s);
    }
}

// ---------------------------------------------------------------------------
// Stage 2: out[i][j] = sum_k shi[i][k] * shi[1024+j][k]
// grid (16 j, 8 i): CTA 128i x 64j, 512 threads (warp tile 32i x 16j).
// smem: AHI +0 (32KB), BHI +32768 (16KB) = 48KB, cp.async 2 K-half groups.
// ---------------------------------------------------------------------------
__global__ __launch_bounds__(512, 1) void stage2(float* __restrict__ out) {
    extern __shared__ char smem[];
    const uint32_t sb = su32(smem);
    const int t = threadIdx.x, lane = t & 31, wid = t >> 5;
    const int it = blockIdx.y * 128, jt = blockIdx.x * 64;
    const int wy = wid & 3, wx = wid >> 2;
    const int m0w = wy * 32, n0w = wx * 16;

    // two K-half commit groups: group cc covers kh [cc*64, cc*64+64)
    #pragma unroll
    for (int cc = 0; cc < 2; cc++) {
        #pragma unroll
        for (int i = 0; i < 2; i++) {
            int idx = t + i * 512;                 // 0..1023
            int row = idx >> 3, c = (idx & 7) + cc * 8;
            uint32_t off = swz2(row, c * 8);
            cp16(sb + off, &g_shi[(size_t)(it + row) * NF + c * 8]);
        }
        {
            int row = t >> 3, c = (t & 7) + cc * 8;   // 512 -> 64 rows
            uint32_t off = swz2(row, c * 8);
            cp16(sb + 32768 + off, &g_shi[(size_t)(1024 + jt + row) * NF + c * 8]);
        }
        CP_COMMIT();
    }

    const int aRow = lane & 15, aK = (lane >> 4) << 3;
    const int bN = ((lane >> 4) << 3) + (lane & 7), bK = ((lane >> 3) & 1) << 3;

    float acc[2][2][4];
    #pragma unroll
    for (int i = 0; i < 2; i++)
        #pragma unroll
        for (int j = 0; j < 2; j++)
            #pragma unroll
            for (int q = 0; q < 4; q++) acc[i][j][q] = 0.f;

    CP_WAIT1();
    __syncthreads();

    #pragma unroll
    for (int half = 0; half < 2; half++) {
        #pragma unroll
        for (int k16 = 0; k16 < 4; k16++) {
            const int kh = half * 64 + k16 * 16;
            uint32_t ah[2][4], bh[4];
            #pragma unroll
            for (int mt = 0; mt < 2; mt++) {
                uint32_t ra = sb + swz2(m0w + mt * 16 + aRow, kh + aK);
                LDSM4(ah[mt], ra);
            }
            {
                uint32_t rb = sb + 32768 + swz2(n0w + bN, kh + bK);
                LDSM4(bh, rb);
            }
            #pragma unroll
            for (int mt = 0; mt < 2; mt++)
                #pragma unroll
                for (int nt = 0; nt < 2; nt++) {
                    uint32_t h0 = bh[nt * 2], h1 = bh[nt * 2 + 1];
                    MMA(acc[mt][nt], ah[mt], h0, h1);
                }
        }
        if (half == 0) {
            CP_WAIT0();
            __syncthreads();
        }
    }

    #pragma unroll
    for (int mt = 0; mt < 2; mt++)
        #pragma unroll
        for (int nt = 0; nt < 2; nt++) {
            int r = it + m0w + mt * 16 + (lane >> 2);
            int cc = jt + n0w + nt * 8 + (lane & 3) * 2;
            *(float2*)&out[(size_t)r * NROW + cc] =
                make_float2(acc[mt][nt][0], acc[mt][nt][1]);
            *(float2*)&out[(size_t)(r + 8) * NROW + cc] =
                make_float2(acc[mt][nt][2], acc[mt][nt][3]);
        }
}

// ---------------------------------------------------------------------------
extern "C" void kernel_launch(void* const* d_in, const int* in_sizes, int n_in,
                              void* d_out, int out_size) {
    (void)in_sizes; (void)n_in; (void)out_size;
    const float* a = (const float*)d_in[0];
    const float* b = (const float*)d_in[1];
    const float* f = (const float*)d_in[2];
    float* out = (float*)d_out;

    cudaFuncSetAttribute(stage1, cudaFuncAttributeMaxDynamicSharedMemorySize, 65536);
    cudaFuncSetAttribute(stage2, cudaFuncAttributeMaxDynamicSharedMemorySize, 49152);

    stage1<<<dim3(MTILES, SPLITK), 512, 65536>>>(a, b, f);
    stage2<<<dim3(16, 8), 512, 49152>>>(out);
}

// round 12
// speedup vs baseline: 1.2429x; 1.1366x over previous
#include <cuda_runtime.h>
#include <cuda_fp16.h>
#include <cstdint>

#define NROW 1024
#define KDIM 2048
#define NF   128
#define SPLITK 8
#define KCHUNK (KDIM / SPLITK)   // 256
#define BK 64
#define MTILES 16

// ---------------------------------------------------------------------------
// Device scratch
// ---------------------------------------------------------------------------
__device__ __half g_ph[SPLITK * 2048 * NF];      // fp16 split-K partials [ks][m][n]
__device__ __half g_shi[2048 * NF];              // relu(scores) fp16, [m][k]

// ---------------------------------------------------------------------------
// Helpers
// ---------------------------------------------------------------------------
__device__ __forceinline__ uint32_t su32(const void* p) {
    return (uint32_t)__cvta_generic_to_shared(p);
}
__device__ __forceinline__ uint32_t pk(__half a, __half b) {
    __half2 h = __halves2half2(a, b);
    return *reinterpret_cast<uint32_t*>(&h);
}
__device__ __forceinline__ void cp16(uint32_t dst, const void* src) {
    asm volatile("cp.async.ca.shared.global [%0], [%1], 16;" :: "r"(dst), "l"(src));
}

#define CP_COMMIT() asm volatile("cp.async.commit_group;" ::: "memory")
#define CP_WAIT0()  asm volatile("cp.async.wait_group 0;"  ::: "memory")
#define CP_WAIT1()  asm volatile("cp.async.wait_group 1;"  ::: "memory")

#define LDSM4(R, addr) \
    asm volatile("ldmatrix.sync.aligned.m8n8.x4.shared.b16 {%0,%1,%2,%3}, [%4];" \
        : "=r"((R)[0]), "=r"((R)[1]), "=r"((R)[2]), "=r"((R)[3]) : "r"(addr))

#define MMA(C, A, b0, b1) \
    asm volatile("mma.sync.aligned.m16n8k16.row.col.f32.f16.f16.f32 " \
        "{%0,%1,%2,%3}, {%4,%5,%6,%7}, {%8,%9}, {%0,%1,%2,%3};" \
        : "+f"((C)[0]), "+f"((C)[1]), "+f"((C)[2]), "+f"((C)[3]) \
        : "r"((A)[0]), "r"((A)[1]), "r"((A)[2]), "r"((A)[3]), "r"(b0), "r"(b1))

// swizzled byte offset, 128B rows (64 halves)
__device__ __forceinline__ uint32_t swz1(int row, int kh) {
    return (uint32_t)(row * 128 + ((((kh >> 3) ^ (row & 7)) << 4)));
}
// swizzled byte offset, 256B rows (128 halves)
__device__ __forceinline__ uint32_t swz2(int row, int kh) {
    int c = kh >> 3;
    return (uint32_t)(row * 256 + ((((c & 8) | ((c ^ (row & 7)) & 7)) << 4)));
}

__device__ __forceinline__ uint2 round4(float4 v) {
    uint2 hw;
    hw.x = pk(__float2half_rn(v.x), __float2half_rn(v.y));
    hw.y = pk(__float2half_rn(v.z), __float2half_rn(v.w));
    return hw;
}

// ---------------------------------------------------------------------------
// Stage 1: partial[ks][m 128-tile][0..127] = X[m, kchunk] . feats^T (fp16 MMA)
// grid (16 m, 8 ks), 512 threads (16 warps, warp tile 32m x 32n).
// X and F both converted inline from fp32 (no prep kernel).
// smem per buffer (32768B): X +0 (16KB), F +16384 (16KB); two buffers = 64KB.
// Epilogue: partials rounded to fp16 (halves the round-trip traffic).
// ---------------------------------------------------------------------------
__global__ __launch_bounds__(512, 1) void stage1(const float* __restrict__ A_,
                                                 const float* __restrict__ B_,
                                                 const float* __restrict__ F_) {
    extern __shared__ char smem[];
    const int t = threadIdx.x, lane = t & 31, wid = t >> 5;
    const uint32_t sb = su32(smem);
    const int m0 = blockIdx.x * 128;
    const int ks = blockIdx.y;
    const float* X = (m0 < NROW) ? A_ : B_;
    const int mb = (m0 < NROW) ? m0 : m0 - NROW;
    const int kbase = ks * KCHUNK;

    const int wy = wid & 3, wx = wid >> 2;
    const int m0w = wy * 32, n0w = wx * 32;
    const int aRow = lane & 15, aK = (lane >> 4) << 3;
    const int bN = ((lane >> 4) << 3) + (lane & 7), bK = ((lane >> 3) & 1) << 3;

    float acc[2][4][4];
    #pragma unroll
    for (int i = 0; i < 2; i++)
        #pragma unroll
        for (int j = 0; j < 4; j++)
            #pragma unroll
            for (int q = 0; q < 4; q++) acc[i][j][q] = 0.f;

    float xr[2][8], fr[2][8];

    // per-thread tile coords (constant across slabs): 128 rows x 8 chunks
    int rows_[2], cs_[2];
    #pragma unroll
    for (int i = 0; i < 2; i++) {
        int chunk = t + i * 512;
        rows_[i] = chunk >> 3;
        cs_[i]   = chunk & 7;
    }

    // ---- slab 0 prologue ----
    {
        const int kk = kbase;
        #pragma unroll
        for (int i = 0; i < 2; i++) {
            const float* sx = &X[(size_t)(mb + rows_[i]) * KDIM + kk + cs_[i] * 8];
            const float* sf = &F_[(size_t)rows_[i] * KDIM + kk + cs_[i] * 8];
            *(float4*)&xr[i][0] = *(const float4*)sx;
            *(float4*)&xr[i][4] = *(const float4*)(sx + 4);
            *(float4*)&fr[i][0] = *(const float4*)sf;
            *(float4*)&fr[i][4] = *(const float4*)(sf + 4);
        }
        #pragma unroll
        for (int i = 0; i < 2; i++) {
            uint32_t off = (uint32_t)(rows_[i] * 128 + (((cs_[i] ^ (rows_[i] & 7)) << 4)));
            uint2 x0 = round4(*(float4*)&xr[i][0]);
            uint2 x1 = round4(*(float4*)&xr[i][4]);
            uint2 f0 = round4(*(float4*)&fr[i][0]);
            uint2 f1 = round4(*(float4*)&fr[i][4]);
            *(uint4*)(smem + off)         = make_uint4(x0.x, x0.y, x1.x, x1.y);
            *(uint4*)(smem + 16384 + off) = make_uint4(f0.x, f0.y, f1.x, f1.y);
        }
        __syncthreads();
    }

    // ---- main loop over 4 slabs ----
    #pragma unroll 1
    for (int s = 0; s < 4; s++) {
        const int p = s & 1, np = p ^ 1;
        if (s < 3) {
            const int kk = kbase + (s + 1) * BK;
            #pragma unroll
            for (int i = 0; i < 2; i++) {
                const float* sx = &X[(size_t)(mb + rows_[i]) * KDIM + kk + cs_[i] * 8];
                const float* sf = &F_[(size_t)rows_[i] * KDIM + kk + cs_[i] * 8];
                *(float4*)&xr[i][0] = *(const float4*)sx;
                *(float4*)&xr[i][4] = *(const float4*)(sx + 4);
                *(float4*)&fr[i][0] = *(const float4*)sf;
                *(float4*)&fr[i][4] = *(const float4*)(sf + 4);
            }
        }

        const uint32_t base = sb + p * 32768;
        #pragma unroll
        for (int k16 = 0; k16 < 4; k16++) {
            const int kh = k16 * 16;
            uint32_t ah[2][4], bh[2][4];
            #pragma unroll
            for (int mt = 0; mt < 2; mt++) {
                uint32_t ra = base + swz1(m0w + mt * 16 + aRow, kh + aK);
                LDSM4(ah[mt], ra);
            }
            #pragma unroll
            for (int g = 0; g < 2; g++) {
                uint32_t rb = base + 16384 + swz1(n0w + g * 16 + bN, kh + bK);
                LDSM4(bh[g], rb);
            }
            #pragma unroll
            for (int mt = 0; mt < 2; mt++)
                #pragma unroll
                for (int nt = 0; nt < 4; nt++) {
                    uint32_t h0 = bh[nt >> 1][(nt & 1) * 2], h1 = bh[nt >> 1][(nt & 1) * 2 + 1];
                    MMA(acc[mt][nt], ah[mt], h0, h1);
                }
        }

        if (s < 3) {
            const uint32_t nboff = (uint32_t)(np * 32768);
            #pragma unroll
            for (int i = 0; i < 2; i++) {
                uint32_t off = nboff + (uint32_t)(rows_[i] * 128 + (((cs_[i] ^ (rows_[i] & 7)) << 4)));
                uint2 x0 = round4(*(float4*)&xr[i][0]);
                uint2 x1 = round4(*(float4*)&xr[i][4]);
                uint2 f0 = round4(*(float4*)&fr[i][0]);
                uint2 f1 = round4(*(float4*)&fr[i][4]);
                *(uint4*)(smem + off)         = make_uint4(x0.x, x0.y, x1.x, x1.y);
                *(uint4*)(smem + 16384 + off) = make_uint4(f0.x, f0.y, f1.x, f1.y);
            }
        }
        __syncthreads();
    }

    // ---- epilogue: write fp16 partials (4B per pair) ----
    __half* dst = g_ph + (size_t)ks * (2048 * NF);
    #pragma unroll
    for (int mt = 0; mt < 2; mt++)
        #pragma unroll
        for (int nt = 0; nt < 4; nt++) {
            int r = m0 + m0w + mt * 16 + (lane >> 2);
            int cc = n0w + nt * 8 + (lane & 3) * 2;
            *(uint32_t*)&dst[(size_t)r * NF + cc] =
                pk(__float2half_rn(acc[mt][nt][0]), __float2half_rn(acc[mt][nt][1]));
            *(uint32_t*)&dst[(size_t)(r + 8) * NF + cc] =
                pk(__float2half_rn(acc[mt][nt][2]), __float2half_rn(acc[mt][nt][3]));
        }
}

// ---------------------------------------------------------------------------
// Reduce: sum fp16 split-K partials in fp32, relu, round to fp16
// ---------------------------------------------------------------------------
__global__ void reduce_relu() {
    int g = blockIdx.x * blockDim.x + threadIdx.x;   // 65536 threads
    size_t o = (size_t)g * 4;
    float4 s = make_float4(0.f, 0.f, 0.f, 0.f);
    #pragma unroll
    for (int p = 0; p < SPLITK; p++) {
        uint2 v = *(const uint2*)&g_ph[(size_t)p * (2048 * NF) + o];
        __half2 h0 = *reinterpret_cast<__half2*>(&v.x);
        __half2 h1 = *reinterpret_cast<__half2*>(&v.y);
        float2 f0 = __half22float2(h0);
        float2 f1 = __half22float2(h1);
        s.x += f0.x; s.y += f0.y; s.z += f1.x; s.w += f1.y;
    }
    s.x = fmaxf(s.x, 0.f); s.y = fmaxf(s.y, 0.f);
    s.z = fmaxf(s.z, 0.f); s.w = fmaxf(s.w, 0.f);
    *(uint2*)&g_shi[o] = round4(s);
}

// ---------------------------------------------------------------------------
// Stage 2: out[i][j] = sum_k shi[i][k] * shi[1024+j][k]
// grid (16 j, 8 i): CTA 128i x 64j, 512 threads (warp tile 32i x 16j).
// smem: AHI +0 (32KB), BHI +32768 (16KB) = 48KB, cp.async 2 K-half groups.
// ---------------------------------------------------------------------------
__global__ __launch_bounds__(512, 1) void stage2(float* __restrict__ out) {
    extern __shared__ char smem[];
    const uint32_t sb = su32(smem);
    const int t = threadIdx.x, lane = t & 31, wid = t >> 5;
    const int it = blockIdx.y * 128, jt = blockIdx.x * 64;
    const int wy = wid & 3, wx = wid >> 2;
    const int m0w = wy * 32, n0w = wx * 16;

    // two K-half commit groups: group cc covers kh [cc*64, cc*64+64)
    #pragma unroll
    for (int cc = 0; cc < 2; cc++) {
        #pragma unroll
        for (int i = 0; i < 2; i++) {
            int idx = t + i * 512;                 // 0..1023
            int row = idx >> 3, c = (idx & 7) + cc * 8;
            uint32_t off = swz2(row, c * 8);
            cp16(sb + off, &g_shi[(size_t)(it + row) * NF + c * 8]);
        }
        {
            int row = t >> 3, c = (t & 7) + cc * 8;   // 512 -> 64 rows
            uint32_t off = swz2(row, c * 8);
            cp16(sb + 32768 + off, &g_shi[(size_t)(1024 + jt + row) * NF + c * 8]);
        }
        CP_COMMIT();
    }

    const int aRow = lane & 15, aK = (lane >> 4) << 3;
    const int bN = ((lane >> 4) << 3) + (lane & 7), bK = ((lane >> 3) & 1) << 3;

    float acc[2][2][4];
    #pragma unroll
    for (int i = 0; i < 2; i++)
        #pragma unroll
        for (int j = 0; j < 2; j++)
            #pragma unroll
            for (int q = 0; q < 4; q++) acc[i][j][q] = 0.f;

    CP_WAIT1();
    __syncthreads();

    #pragma unroll
    for (int half = 0; half < 2; half++) {
        #pragma unroll
        for (int k16 = 0; k16 < 4; k16++) {
            const int kh = half * 64 + k16 * 16;
            uint32_t ah[2][4], bh[4];
            #pragma unroll
            for (int mt = 0; mt < 2; mt++) {
                uint32_t ra = sb + swz2(m0w + mt * 16 + aRow, kh + aK);
                LDSM4(ah[mt], ra);
            }
            {
                uint32_t rb = sb + 32768 + swz2(n0w + bN, kh + bK);
                LDSM4(bh, rb);
            }
            #pragma unroll
            for (int mt = 0; mt < 2; mt++)
                #pragma unroll
                for (int nt = 0; nt < 2; nt++) {
                    uint32_t h0 = bh[nt * 2], h1 = bh[nt * 2 + 1];
                    MMA(acc[mt][nt], ah[mt], h0, h1);
                }
        }
        if (half == 0) {
            CP_WAIT0();
            __syncthreads();
        }
    }

    #pragma unroll
    for (int mt = 0; mt < 2; mt++)
        #pragma unroll
        for (int nt = 0; nt < 2; nt++) {
            int r = it + m0w + mt * 16 + (lane >> 2);
            int cc = jt + n0w + nt * 8 + (lane & 3) * 2;
            *(float2*)&out[(size_t)r * NROW + cc] =
                make_float2(acc[mt][nt][0], acc[mt][nt][1]);
            *(float2*)&out[(size_t)(r + 8) * NROW + cc] =
                make_float2(acc[mt][nt][2], acc[mt][nt][3]);
        }
}

// ---------------------------------------------------------------------------
extern "C" void kernel_launch(void* const* d_in, const int* in_sizes, int n_in,
                              void* d_out, int out_size) {
    (void)in_sizes; (void)n_in; (void)out_size;
    const float* a = (const float*)d_in[0];
    const float* b = (const float*)d_in[1];
    const float* f = (const float*)d_in[2];
    float* out = (float*)d_out;

    cudaFuncSetAttribute(stage1, cudaFuncAttributeMaxDynamicSharedMemorySize, 65536);
    cudaFuncSetAttribute(stage2, cudaFuncAttributeMaxDynamicSharedMemorySize, 49152);

    stage1<<<dim3(MTILES, SPLITK), 512, 65536>>>(a, b, f);
    reduce_relu<<<256, 256>>>();
    stage2<<<dim3(16, 8), 512, 49152>>>(out);
}